// round 3
// baseline (speedup 1.0000x reference)
#include <cuda_runtime.h>

#define BB 16
#define NN 4096
#define SS 1024
#define KK 32
#define NPOS (BB*SS*KK)      /* 524288 */
#define OUT1 (BB*3*SS)       /* 49152  */
#define R2C 0.04f
#define EPSV 1e-5f

typedef unsigned long long ull;

// ---------------- scratch (device globals; no allocation allowed) ----------
__device__ float g_new_xyz[BB*SS*3];
__device__ int   g_ball[NPOS];
__device__ __align__(16) float g_y1[64*NPOS];    // 134 MB
__device__ __align__(16) float g_y2[128*NPOS];   // 268 MB
__device__ float g_xstat[27];      // 6 sums + 21 sym second moments
__device__ float g_s1[128];        // sum[64], sumsq[64]
__device__ float g_s2[256];        // sum[128], sumsq[128]
__device__ float g_sc0[64], g_sh0[64];
__device__ float g_sc1[64], g_sh1[64];
__device__ float g_sc2[128], g_sh2[128];

// ---------------- f32x2 helpers (Blackwell packed FFMA2) -------------------
__device__ __forceinline__ ull pack2(float lo, float hi) {
    ull r; asm("mov.b64 %0, {%1,%2};" : "=l"(r) : "f"(lo), "f"(hi)); return r;
}
__device__ __forceinline__ void unpack2(ull v, float& lo, float& hi) {
    asm("mov.b64 {%0,%1}, %2;" : "=f"(lo), "=f"(hi) : "l"(v));
}
__device__ __forceinline__ ull fma2(ull a, ull b, ull c) {
    ull d; asm("fma.rn.f32x2 %0, %1, %2, %3;" : "=l"(d) : "l"(a), "l"(b), "l"(c));
    return d;
}
__device__ __forceinline__ float wredsum(float v) {
    #pragma unroll
    for (int o = 16; o; o >>= 1) v += __shfl_down_sync(0xffffffffu, v, o);
    return v;
}

// ---------------- K0: zero stats -------------------------------------------
__global__ void k_zero() {
    int t = threadIdx.x;
    if (t < 27)  g_xstat[t] = 0.f;
    if (t < 128) g_s1[t] = 0.f;
    if (t < 256) g_s2[t] = 0.f;
}

// ---------------- K1: farthest point sampling ------------------------------
__global__ void __launch_bounds__(1024) k_fps(const float* __restrict__ xyz,
                                              float* __restrict__ out) {
    int b = blockIdx.x, t = threadIdx.x;
    const float* X = xyz + b * 3 * NN;
    float px[4], py[4], pz[4], dd[4];
    #pragma unroll
    for (int i = 0; i < 4; i++) {
        int n = t + i * 1024;
        px[i] = X[n]; py[i] = X[NN + n]; pz[i] = X[2 * NN + n];
        dd[i] = 1e10f;
    }
    __shared__ float scx, scy, scz;
    __shared__ int sF;
    __shared__ float swv[32];
    __shared__ int   swi[32];
    if (t == 0) sF = 0;
    __syncthreads();

    for (int it = 0; it < SS; it++) {
        int f = sF;
        int owner = f & 1023, slot = f >> 10;
        if (t == owner) { scx = px[slot]; scy = py[slot]; scz = pz[slot]; }
        __syncthreads();
        float cx = scx, cy = scy, cz = scz;
        if (t == 0) {
            int base = (b * SS + it) * 3;
            g_new_xyz[base + 0] = cx; g_new_xyz[base + 1] = cy; g_new_xyz[base + 2] = cz;
            out[b * 3 * SS + it]           = cx;
            out[b * 3 * SS + SS + it]      = cy;
            out[b * 3 * SS + 2 * SS + it]  = cz;
        }
        float bv = -1.f; int bi = 0x7fffffff;
        #pragma unroll
        for (int i = 0; i < 4; i++) {
            float dx = px[i] - cx, dy = py[i] - cy, dz = pz[i] - cz;
            float d = __fadd_rn(__fadd_rn(__fmul_rn(dx, dx), __fmul_rn(dy, dy)),
                                __fmul_rn(dz, dz));
            float nd = fminf(dd[i], d); dd[i] = nd;
            int idx = t + i * 1024;
            if (nd > bv || (nd == bv && idx < bi)) { bv = nd; bi = idx; }
        }
        #pragma unroll
        for (int off = 16; off; off >>= 1) {
            float ov = __shfl_down_sync(0xffffffffu, bv, off);
            int   oi = __shfl_down_sync(0xffffffffu, bi, off);
            if (ov > bv || (ov == bv && oi < bi)) { bv = ov; bi = oi; }
        }
        if ((t & 31) == 0) { swv[t >> 5] = bv; swi[t >> 5] = bi; }
        __syncthreads();
        if (t < 32) {
            bv = swv[t]; bi = swi[t];
            #pragma unroll
            for (int off = 16; off; off >>= 1) {
                float ov = __shfl_down_sync(0xffffffffu, bv, off);
                int   oi = __shfl_down_sync(0xffffffffu, bi, off);
                if (ov > bv || (ov == bv && oi < bi)) { bv = ov; bi = oi; }
            }
            if (t == 0) sF = bi;
        }
        __syncthreads();
    }
}

// ---------------- K2: ball query (warp per centroid) -----------------------
__global__ void k_ball(const float* __restrict__ xyz) {
    int gt = blockIdx.x * blockDim.x + threadIdx.x;
    int w = gt >> 5, lane = gt & 31;
    int b = w >> 10;
    float cx = g_new_xyz[w * 3 + 0], cy = g_new_xyz[w * 3 + 1], cz = g_new_xyz[w * 3 + 2];
    float s1 = __fadd_rn(__fadd_rn(__fmul_rn(cx, cx), __fmul_rn(cy, cy)), __fmul_rn(cz, cz));
    const float* X = xyz + b * 3 * NN;
    int* dst = g_ball + w * KK;
    int cnt = 0, first = 0;
    bool haveFirst = false;
    for (int base = 0; base < NN; base += 32) {
        int n = base + lane;
        float px = X[n], py = X[NN + n], pz = X[2 * NN + n];
        float dot = __fadd_rn(__fadd_rn(__fmul_rn(cx, px), __fmul_rn(cy, py)), __fmul_rn(cz, pz));
        float s2 = __fadd_rn(__fadd_rn(__fmul_rn(px, px), __fmul_rn(py, py)), __fmul_rn(pz, pz));
        float d = __fadd_rn(__fadd_rn(__fmul_rn(-2.f, dot), s1), s2);
        bool in = (d <= R2C);
        unsigned m = __ballot_sync(0xffffffffu, in);
        if (!haveFirst && m) { first = base + __ffs(m) - 1; haveFirst = true; }
        int pos = cnt + __popc(m & ((1u << lane) - 1));
        if (in && pos < KK) dst[pos] = n;
        cnt += __popc(m);
        if (cnt >= KK) break;
    }
    int filled = min(cnt, KK);
    for (int j = filled + lane; j < KK; j += 32) dst[j] = first;
}

// ---------------- K3: input moment accumulation ----------------------------
__global__ void k_xstat(const float* __restrict__ xyz, const float* __restrict__ pts) {
    int p = blockIdx.x * blockDim.x + threadIdx.x;
    int b = p >> 15, s = (p >> 5) & 1023;
    int j = g_ball[p];
    int c3 = (b * SS + s) * 3;
    float cx = g_new_xyz[c3], cy = g_new_xyz[c3 + 1], cz = g_new_xyz[c3 + 2];
    const float* X = xyz + b * 3 * NN;
    const float* P = pts + b * 3 * NN;
    float x[6];
    x[0] = X[j] - cx; x[1] = X[NN + j] - cy; x[2] = X[2 * NN + j] - cz;
    x[3] = P[j];      x[4] = P[NN + j];      x[5] = P[2 * NN + j];
    float v[27];
    #pragma unroll
    for (int c = 0; c < 6; c++) v[c] = x[c];
    int idx = 6;
    #pragma unroll
    for (int c0 = 0; c0 < 6; c0++)
        #pragma unroll
        for (int c1 = c0; c1 < 6; c1++) v[idx++] = x[c0] * x[c1];

    __shared__ float acc[27];
    if (threadIdx.x < 27) acc[threadIdx.x] = 0.f;
    __syncthreads();
    #pragma unroll
    for (int i = 0; i < 27; i++) {
        float tt = wredsum(v[i]);
        if ((threadIdx.x & 31) == 0) atomicAdd(&acc[i], tt);
    }
    __syncthreads();
    if (threadIdx.x < 27) atomicAdd(&g_xstat[threadIdx.x], acc[threadIdx.x]);
}

// ---------------- K4: analytic BN0 stats -----------------------------------
__global__ void k_fin0(const float* __restrict__ w0, const float* __restrict__ b0,
                       const float* __restrict__ g0, const float* __restrict__ be0) {
    int o = threadIdx.x;
    if (o >= 64) return;
    float inv = 1.f / (float)NPOS;
    float mx[6], M[6][6];
    for (int c = 0; c < 6; c++) mx[c] = g_xstat[c] * inv;
    int idx = 6;
    for (int c0 = 0; c0 < 6; c0++)
        for (int c1 = c0; c1 < 6; c1++) {
            float m = g_xstat[idx++] * inv;
            M[c0][c1] = m; M[c1][c0] = m;
        }
    float W[6];
    for (int c = 0; c < 6; c++) W[c] = w0[o * 6 + c];
    float wm = 0.f;
    for (int c = 0; c < 6; c++) wm += W[c] * mx[c];
    float quad = 0.f;
    for (int c0 = 0; c0 < 6; c0++)
        for (int c1 = 0; c1 < 6; c1++) quad += W[c0] * W[c1] * M[c0][c1];
    float mean = wm + b0[o];
    float var = quad - wm * wm;
    float sc = g0[o] * rsqrtf(var + EPSV);
    g_sc0[o] = sc;
    g_sh0[o] = be0[o] - mean * sc;
}

// ---------------- K5: fused gather + conv0 + BN0 + GEMM1 -------------------
__global__ void __launch_bounds__(256) k_layer1(
    const float* __restrict__ xyz, const float* __restrict__ pts,
    const float* __restrict__ w0, const float* __restrict__ b0,
    const float* __restrict__ w1, const float* __restrict__ b1)
{
    __shared__ __align__(16) float Zsh[64][128];   // z0 (post BN+relu), 32 KB
    __shared__ __align__(16) float Wsh[32][68];    // padded W1 chunk, 8.5 KB
    int t = threadIdx.x;
    int pbase = blockIdx.x * 128;

    if (t < 128) {
        int p = pbase + t;
        int b = p >> 15, s = (p >> 5) & 1023;
        int j = g_ball[p];
        int c3 = (b * SS + s) * 3;
        float cx = g_new_xyz[c3], cy = g_new_xyz[c3 + 1], cz = g_new_xyz[c3 + 2];
        const float* X = xyz + b * 3 * NN;
        const float* P = pts + b * 3 * NN;
        float x0 = X[j] - cx, x1 = X[NN + j] - cy, x2 = X[2 * NN + j] - cz;
        float x3 = P[j], x4 = P[NN + j], x5 = P[2 * NN + j];
        #pragma unroll 8
        for (int o = 0; o < 64; o++) {
            const float* wr = w0 + o * 6;
            float a = b0[o];
            a = fmaf(wr[0], x0, a); a = fmaf(wr[1], x1, a); a = fmaf(wr[2], x2, a);
            a = fmaf(wr[3], x3, a); a = fmaf(wr[4], x4, a); a = fmaf(wr[5], x5, a);
            float z = fmaf(a, g_sc0[o], g_sh0[o]);
            Zsh[o][t] = fmaxf(z, 0.f);
        }
    }

    int po = t & 31, og = t >> 5;
    int o0 = og * 8;
    ull acc[4][4];
    #pragma unroll
    for (int op = 0; op < 4; op++) {
        ull bb = pack2(b1[o0 + 2 * op], b1[o0 + 2 * op + 1]);
        #pragma unroll
        for (int pp = 0; pp < 4; pp++) acc[op][pp] = bb;
    }

    for (int ch = 0; ch < 64; ch += 32) {
        __syncthreads();
        for (int L = t; L < 4096; L += 256) {
            int o = L >> 6, c = L & 63;
            if ((c & 32) == ch) Wsh[c & 31][o] = w1[L];
        }
        __syncthreads();
        #pragma unroll
        for (int cc = 0; cc < 32; cc++) {
            float4 z4 = *reinterpret_cast<const float4*>(&Zsh[ch + cc][po << 2]);
            ull zd[4] = { pack2(z4.x, z4.x), pack2(z4.y, z4.y),
                          pack2(z4.z, z4.z), pack2(z4.w, z4.w) };
            const ulonglong2* wp = reinterpret_cast<const ulonglong2*>(&Wsh[cc][o0]);
            ulonglong2 wA = wp[0], wB = wp[1];
            ull wv[4] = { wA.x, wA.y, wB.x, wB.y };
            #pragma unroll
            for (int op = 0; op < 4; op++)
                #pragma unroll
                for (int pp = 0; pp < 4; pp++)
                    acc[op][pp] = fma2(wv[op], zd[pp], acc[op][pp]);
        }
    }

    int pcol = pbase + (po << 2);
    float sum[8], sq[8];
    #pragma unroll
    for (int op = 0; op < 4; op++) {
        float lo[4], hi[4];
        #pragma unroll
        for (int pp = 0; pp < 4; pp++) unpack2(acc[op][pp], lo[pp], hi[pp]);
        float4 v0 = { lo[0], lo[1], lo[2], lo[3] };
        float4 v1 = { hi[0], hi[1], hi[2], hi[3] };
        *reinterpret_cast<float4*>(&g_y1[(o0 + 2 * op) * NPOS + pcol]) = v0;
        *reinterpret_cast<float4*>(&g_y1[(o0 + 2 * op + 1) * NPOS + pcol]) = v1;
        sum[2 * op]     = lo[0] + lo[1] + lo[2] + lo[3];
        sum[2 * op + 1] = hi[0] + hi[1] + hi[2] + hi[3];
        sq[2 * op]      = lo[0]*lo[0] + lo[1]*lo[1] + lo[2]*lo[2] + lo[3]*lo[3];
        sq[2 * op + 1]  = hi[0]*hi[0] + hi[1]*hi[1] + hi[2]*hi[2] + hi[3]*hi[3];
    }
    #pragma unroll
    for (int i = 0; i < 8; i++) { sum[i] = wredsum(sum[i]); sq[i] = wredsum(sq[i]); }
    if ((t & 31) == 0) {
        #pragma unroll
        for (int i = 0; i < 8; i++) {
            atomicAdd(&g_s1[o0 + i], sum[i]);
            atomicAdd(&g_s1[64 + o0 + i], sq[i]);
        }
    }
}

// ---------------- K6/K8: finalize BN stats ---------------------------------
__global__ void k_fin1(const float* __restrict__ g, const float* __restrict__ be) {
    int o = threadIdx.x;
    if (o >= 64) return;
    float inv = 1.f / (float)NPOS;
    float m = g_s1[o] * inv;
    float var = g_s1[64 + o] * inv - m * m;
    float sc = g[o] * rsqrtf(var + EPSV);
    g_sc1[o] = sc; g_sh1[o] = be[o] - m * sc;
}
__global__ void k_fin2(const float* __restrict__ g, const float* __restrict__ be) {
    int o = threadIdx.x;
    if (o >= 128) return;
    float inv = 1.f / (float)NPOS;
    float m = g_s2[o] * inv;
    float var = g_s2[128 + o] * inv - m * m;
    float sc = g[o] * rsqrtf(var + EPSV);
    g_sc2[o] = sc; g_sh2[o] = be[o] - m * sc;
}

// ---------------- K7: BN1 + relu + GEMM2 (64 -> 128) -----------------------
__global__ void __launch_bounds__(256) k_layer2(const float* __restrict__ w2,
                                                const float* __restrict__ b2)
{
    __shared__ __align__(16) float Zsh[32][128];   // 16 KB chunk
    __shared__ __align__(16) float Wsh[32][132];   // padded, 16.5 KB chunk
    int t = threadIdx.x;
    int pbase = blockIdx.x * 128;
    int po = t & 31, og = t >> 5;
    int o0 = og * 16;

    ull acc[8][4];
    #pragma unroll
    for (int op = 0; op < 8; op++) {
        ull bb = pack2(b2[o0 + 2 * op], b2[o0 + 2 * op + 1]);
        #pragma unroll
        for (int pp = 0; pp < 4; pp++) acc[op][pp] = bb;
    }

    for (int ch = 0; ch < 64; ch += 32) {
        __syncthreads();
        for (int i = t; i < 4096; i += 256) {
            int c = i >> 7, pc = i & 127;
            float y = g_y1[(ch + c) * NPOS + pbase + pc];
            Zsh[c][pc] = fmaxf(fmaf(y, g_sc1[ch + c], g_sh1[ch + c]), 0.f);
        }
        for (int L = t; L < 8192; L += 256) {
            int o = L >> 6, c = L & 63;
            if ((c & 32) == ch) Wsh[c & 31][o] = w2[L];
        }
        __syncthreads();
        #pragma unroll
        for (int cc = 0; cc < 32; cc++) {
            float4 z4 = *reinterpret_cast<const float4*>(&Zsh[cc][po << 2]);
            ull zd[4] = { pack2(z4.x, z4.x), pack2(z4.y, z4.y),
                          pack2(z4.z, z4.z), pack2(z4.w, z4.w) };
            const ulonglong2* wp = reinterpret_cast<const ulonglong2*>(&Wsh[cc][o0]);
            ulonglong2 wA = wp[0], wB = wp[1], wC = wp[2], wD = wp[3];
            ull wv[8] = { wA.x, wA.y, wB.x, wB.y, wC.x, wC.y, wD.x, wD.y };
            #pragma unroll
            for (int op = 0; op < 8; op++)
                #pragma unroll
                for (int pp = 0; pp < 4; pp++)
                    acc[op][pp] = fma2(wv[op], zd[pp], acc[op][pp]);
        }
    }

    int pcol = pbase + (po << 2);
    float sum[16], sq[16];
    #pragma unroll
    for (int op = 0; op < 8; op++) {
        float lo[4], hi[4];
        #pragma unroll
        for (int pp = 0; pp < 4; pp++) unpack2(acc[op][pp], lo[pp], hi[pp]);
        float4 v0 = { lo[0], lo[1], lo[2], lo[3] };
        float4 v1 = { hi[0], hi[1], hi[2], hi[3] };
        *reinterpret_cast<float4*>(&g_y2[(o0 + 2 * op) * NPOS + pcol]) = v0;
        *reinterpret_cast<float4*>(&g_y2[(o0 + 2 * op + 1) * NPOS + pcol]) = v1;
        sum[2 * op]     = lo[0] + lo[1] + lo[2] + lo[3];
        sum[2 * op + 1] = hi[0] + hi[1] + hi[2] + hi[3];
        sq[2 * op]      = lo[0]*lo[0] + lo[1]*lo[1] + lo[2]*lo[2] + lo[3]*lo[3];
        sq[2 * op + 1]  = hi[0]*hi[0] + hi[1]*hi[1] + hi[2]*hi[2] + hi[3]*hi[3];
    }
    #pragma unroll
    for (int i = 0; i < 16; i++) { sum[i] = wredsum(sum[i]); sq[i] = wredsum(sq[i]); }
    if ((t & 31) == 0) {
        #pragma unroll
        for (int i = 0; i < 16; i++) {
            atomicAdd(&g_s2[o0 + i], sum[i]);
            atomicAdd(&g_s2[128 + o0 + i], sq[i]);
        }
    }
}

// ---------------- K9: BN2 + relu + max over samples ------------------------
__global__ void k_max(float* __restrict__ out) {
    int m = blockIdx.x * blockDim.x + threadIdx.x;   // 2,097,152 threads
    int b = m >> 17, o = (m >> 10) & 127, s = m & 1023;
    float sc = g_sc2[o], sh = g_sh2[o];
    const float4* src = reinterpret_cast<const float4*>(
        &g_y2[o * NPOS + ((b * SS + s) << 5)]);
    float mx = 0.f;
    #pragma unroll
    for (int i = 0; i < 8; i++) {
        float4 v = src[i];
        mx = fmaxf(mx, fmaxf(fmaf(v.x, sc, sh), 0.f));
        mx = fmaxf(mx, fmaxf(fmaf(v.y, sc, sh), 0.f));
        mx = fmaxf(mx, fmaxf(fmaf(v.z, sc, sh), 0.f));
        mx = fmaxf(mx, fmaxf(fmaf(v.w, sc, sh), 0.f));
    }
    out[OUT1 + m] = mx;
}

// ---------------- launch ---------------------------------------------------
extern "C" void kernel_launch(void* const* d_in, const int* in_sizes, int n_in,
                              void* d_out, int out_size) {
    const float* xyz = (const float*)d_in[0];
    const float* pts = (const float*)d_in[1];
    const float* w0  = (const float*)d_in[2];
    const float* b0  = (const float*)d_in[3];
    const float* g0  = (const float*)d_in[4];
    const float* be0 = (const float*)d_in[5];
    const float* w1  = (const float*)d_in[6];
    const float* b1  = (const float*)d_in[7];
    const float* g1  = (const float*)d_in[8];
    const float* be1 = (const float*)d_in[9];
    const float* w2  = (const float*)d_in[10];
    const float* b2  = (const float*)d_in[11];
    const float* g2  = (const float*)d_in[12];
    const float* be2 = (const float*)d_in[13];
    float* out = (float*)d_out;
    (void)in_sizes; (void)n_in; (void)out_size;

    k_zero   <<<1, 256>>>();
    k_fps    <<<BB, 1024>>>(xyz, out);
    k_ball   <<<(BB * SS * 32) / 256, 256>>>(xyz);
    k_xstat  <<<NPOS / 256, 256>>>(xyz, pts);
    k_fin0   <<<1, 64>>>(w0, b0, g0, be0);
    k_layer1 <<<NPOS / 128, 256>>>(xyz, pts, w0, b0, w1, b1);
    k_fin1   <<<1, 64>>>(g1, be1);
    k_layer2 <<<NPOS / 128, 256>>>(w2, b2);
    k_fin2   <<<1, 128>>>(g2, be2);
    k_max    <<<(BB * 128 * SS) / 256, 256>>>(out);
}

// round 4
// speedup vs baseline: 1.1000x; 1.1000x over previous
#include <cuda_runtime.h>

#define BB 16
#define NN 4096
#define SS 1024
#define KK 32
#define NPOS (BB*SS*KK)      /* 524288 */
#define OUT1 (BB*3*SS)       /* 49152  */
#define NFEAT (BB*128*SS)    /* 2097152 */
#define R2C 0.04f
#define EPSV 1e-5f

typedef unsigned long long ull;

// ---------------- scratch (device globals; no allocation allowed) ----------
__device__ float g_new_xyz[BB*SS*3];
__device__ int   g_ball[NPOS];
__device__ __align__(16) float g_y1[64*NPOS];    // 134 MB
__device__ float g_m2mx[NFEAT];    // raw y2 max over k, 8 MB
__device__ float g_m2mn[NFEAT];    // raw y2 min over k, 8 MB
__device__ float g_xstat[27];
__device__ float g_s1[128];
__device__ float g_s2[256];
__device__ float g_sc0[64], g_sh0[64];
__device__ float g_sc1[64], g_sh1[64];
__device__ float g_sc2[128], g_sh2[128];

// ---------------- f32x2 helpers (Blackwell packed ops) ---------------------
__device__ __forceinline__ ull pack2(float lo, float hi) {
    ull r; asm("mov.b64 %0, {%1,%2};" : "=l"(r) : "f"(lo), "f"(hi)); return r;
}
__device__ __forceinline__ void unpack2(ull v, float& lo, float& hi) {
    asm("mov.b64 {%0,%1}, %2;" : "=f"(lo), "=f"(hi) : "l"(v));
}
__device__ __forceinline__ ull fma2(ull a, ull b, ull c) {
    ull d; asm("fma.rn.f32x2 %0, %1, %2, %3;" : "=l"(d) : "l"(a), "l"(b), "l"(c));
    return d;
}
__device__ __forceinline__ ull add2(ull a, ull b) {
    ull d; asm("add.rn.f32x2 %0, %1, %2;" : "=l"(d) : "l"(a), "l"(b)); return d;
}
__device__ __forceinline__ ull mul2(ull a, ull b) {
    ull d; asm("mul.rn.f32x2 %0, %1, %2;" : "=l"(d) : "l"(a), "l"(b)); return d;
}
__device__ __forceinline__ float wredsum(float v) {
    #pragma unroll
    for (int o = 16; o; o >>= 1) v += __shfl_down_sync(0xffffffffu, v, o);
    return v;
}

// ---------------- K0: zero stats -------------------------------------------
__global__ void k_zero() {
    int t = threadIdx.x;
    if (t < 27)  g_xstat[t] = 0.f;
    if (t < 128) g_s1[t] = 0.f;
    if (t < 256) g_s2[t] = 0.f;
}

// ---------------- K1: farthest point sampling (2 bars/iter, f32x2) ---------
__global__ void __launch_bounds__(1024) k_fps(const float* __restrict__ xyz,
                                              float* __restrict__ out) {
    int b = blockIdx.x, t = threadIdx.x;
    const float* X = xyz + b * 3 * NN;
    __shared__ float sx[NN], sy[NN], sz[NN];   // 48 KB: for centroid fetch
    __shared__ float scx, scy, scz;
    __shared__ float swv[32];
    __shared__ int   swi[32];

    // registers: 4 points per thread, packed in pairs (t,t+1024),(t+2048,t+3072)
    float px[4], py[4], pz[4], dd[4];
    #pragma unroll
    for (int i = 0; i < 4; i++) {
        int n = t + i * 1024;
        px[i] = X[n]; py[i] = X[NN + n]; pz[i] = X[2 * NN + n];
        sx[n] = px[i]; sy[n] = py[i]; sz[n] = pz[i];
        dd[i] = 1e10f;
    }
    ull px2[2] = { pack2(px[0], px[1]), pack2(px[2], px[3]) };
    ull py2[2] = { pack2(py[0], py[1]), pack2(py[2], py[3]) };
    ull pz2[2] = { pack2(pz[0], pz[1]), pack2(pz[2], pz[3]) };

    __syncthreads();                 // smem points visible
    if (t == 0) { scx = sx[0]; scy = sy[0]; scz = sz[0]; }
    __syncthreads();

    int lane = t & 31, wid = t >> 5;
    for (int it = 0; it < SS; it++) {
        float cx = scx, cy = scy, cz = scz;
        if (t == 0) {
            int base = (b * SS + it) * 3;
            g_new_xyz[base + 0] = cx; g_new_xyz[base + 1] = cy; g_new_xyz[base + 2] = cz;
            out[b * 3 * SS + it]          = cx;
            out[b * 3 * SS + SS + it]     = cy;
            out[b * 3 * SS + 2 * SS + it] = cz;
        }
        ull ncx = pack2(-cx, -cx), ncy = pack2(-cy, -cy), ncz = pack2(-cz, -cz);
        float bv = -1.f; int bi = 0x7fffffff;
        #pragma unroll
        for (int j = 0; j < 2; j++) {
            // exact: (p - c) as p + (-c); squares via rn mul; tree (xx+yy)+zz
            ull dx = add2(px2[j], ncx), dy = add2(py2[j], ncy), dz = add2(pz2[j], ncz);
            ull d2 = add2(add2(mul2(dx, dx), mul2(dy, dy)), mul2(dz, dz));
            float d0, d1; unpack2(d2, d0, d1);
            int i0 = 2 * j, i1 = 2 * j + 1;
            float n0 = fminf(dd[i0], d0); dd[i0] = n0;
            int idx0 = t + j * 2048;
            if (n0 > bv) { bv = n0; bi = idx0; }      // strict >: first index wins
            float n1 = fminf(dd[i1], d1); dd[i1] = n1;
            int idx1 = t + j * 2048 + 1024;
            if (n1 > bv) { bv = n1; bi = idx1; }
        }
        #pragma unroll
        for (int off = 1; off < 32; off <<= 1) {
            float ov = __shfl_xor_sync(0xffffffffu, bv, off);
            int   oi = __shfl_xor_sync(0xffffffffu, bi, off);
            if (ov > bv || (ov == bv && oi < bi)) { bv = ov; bi = oi; }
        }
        if (lane == 0) { swv[wid] = bv; swi[wid] = bi; }
        __syncthreads();             // bar 1
        if (t < 32) {
            bv = swv[t]; bi = swi[t];
            #pragma unroll
            for (int off = 1; off < 32; off <<= 1) {
                float ov = __shfl_xor_sync(0xffffffffu, bv, off);
                int   oi = __shfl_xor_sync(0xffffffffu, bi, off);
                if (ov > bv || (ov == bv && oi < bi)) { bv = ov; bi = oi; }
            }
            if (t == 0) { scx = sx[bi]; scy = sy[bi]; scz = sz[bi]; }
        }
        __syncthreads();             // bar 2
    }
}

// ---------------- K2: ball query (warp per centroid) -----------------------
__global__ void k_ball(const float* __restrict__ xyz) {
    int gt = blockIdx.x * blockDim.x + threadIdx.x;
    int w = gt >> 5, lane = gt & 31;
    int b = w >> 10;
    float cx = g_new_xyz[w * 3 + 0], cy = g_new_xyz[w * 3 + 1], cz = g_new_xyz[w * 3 + 2];
    float s1 = __fadd_rn(__fadd_rn(__fmul_rn(cx, cx), __fmul_rn(cy, cy)), __fmul_rn(cz, cz));
    const float* X = xyz + b * 3 * NN;
    int* dst = g_ball + w * KK;
    int cnt = 0, first = 0;
    bool haveFirst = false;
    for (int base = 0; base < NN; base += 32) {
        int n = base + lane;
        float px = X[n], py = X[NN + n], pz = X[2 * NN + n];
        float dot = __fadd_rn(__fadd_rn(__fmul_rn(cx, px), __fmul_rn(cy, py)), __fmul_rn(cz, pz));
        float s2 = __fadd_rn(__fadd_rn(__fmul_rn(px, px), __fmul_rn(py, py)), __fmul_rn(pz, pz));
        float d = __fadd_rn(__fadd_rn(__fmul_rn(-2.f, dot), s1), s2);
        bool in = (d <= R2C);
        unsigned m = __ballot_sync(0xffffffffu, in);
        if (!haveFirst && m) { first = base + __ffs(m) - 1; haveFirst = true; }
        int pos = cnt + __popc(m & ((1u << lane) - 1));
        if (in && pos < KK) dst[pos] = n;
        cnt += __popc(m);
        if (cnt >= KK) break;
    }
    int filled = min(cnt, KK);
    for (int j = filled + lane; j < KK; j += 32) dst[j] = first;
}

// ---------------- K3: input moment accumulation ----------------------------
__global__ void k_xstat(const float* __restrict__ xyz, const float* __restrict__ pts) {
    int p = blockIdx.x * blockDim.x + threadIdx.x;
    int b = p >> 15, s = (p >> 5) & 1023;
    int j = g_ball[p];
    int c3 = (b * SS + s) * 3;
    float cx = g_new_xyz[c3], cy = g_new_xyz[c3 + 1], cz = g_new_xyz[c3 + 2];
    const float* X = xyz + b * 3 * NN;
    const float* P = pts + b * 3 * NN;
    float x[6];
    x[0] = X[j] - cx; x[1] = X[NN + j] - cy; x[2] = X[2 * NN + j] - cz;
    x[3] = P[j];      x[4] = P[NN + j];      x[5] = P[2 * NN + j];
    float v[27];
    #pragma unroll
    for (int c = 0; c < 6; c++) v[c] = x[c];
    int idx = 6;
    #pragma unroll
    for (int c0 = 0; c0 < 6; c0++)
        #pragma unroll
        for (int c1 = c0; c1 < 6; c1++) v[idx++] = x[c0] * x[c1];

    __shared__ float acc[27];
    if (threadIdx.x < 27) acc[threadIdx.x] = 0.f;
    __syncthreads();
    #pragma unroll
    for (int i = 0; i < 27; i++) {
        float tt = wredsum(v[i]);
        if ((threadIdx.x & 31) == 0) atomicAdd(&acc[i], tt);
    }
    __syncthreads();
    if (threadIdx.x < 27) atomicAdd(&g_xstat[threadIdx.x], acc[threadIdx.x]);
}

// ---------------- K4: analytic BN0 stats -----------------------------------
__global__ void k_fin0(const float* __restrict__ w0, const float* __restrict__ b0,
                       const float* __restrict__ g0, const float* __restrict__ be0) {
    int o = threadIdx.x;
    if (o >= 64) return;
    float inv = 1.f / (float)NPOS;
    float mx[6], M[6][6];
    for (int c = 0; c < 6; c++) mx[c] = g_xstat[c] * inv;
    int idx = 6;
    for (int c0 = 0; c0 < 6; c0++)
        for (int c1 = c0; c1 < 6; c1++) {
            float m = g_xstat[idx++] * inv;
            M[c0][c1] = m; M[c1][c0] = m;
        }
    float W[6];
    for (int c = 0; c < 6; c++) W[c] = w0[o * 6 + c];
    float wm = 0.f;
    for (int c = 0; c < 6; c++) wm += W[c] * mx[c];
    float quad = 0.f;
    for (int c0 = 0; c0 < 6; c0++)
        for (int c1 = 0; c1 < 6; c1++) quad += W[c0] * W[c1] * M[c0][c1];
    float mean = wm + b0[o];
    float var = quad - wm * wm;
    float sc = g0[o] * rsqrtf(var + EPSV);
    g_sc0[o] = sc;
    g_sh0[o] = be0[o] - mean * sc;
}

// ---------------- K5: fused gather + conv0 + BN0 + GEMM1 -------------------
__global__ void __launch_bounds__(256) k_layer1(
    const float* __restrict__ xyz, const float* __restrict__ pts,
    const float* __restrict__ w0, const float* __restrict__ b0,
    const float* __restrict__ w1, const float* __restrict__ b1)
{
    __shared__ __align__(16) float Zsh[64][128];   // 32 KB
    __shared__ __align__(16) float Wsh[32][68];    // 8.5 KB
    int t = threadIdx.x;
    int pbase = blockIdx.x * 128;

    if (t < 128) {
        int p = pbase + t;
        int b = p >> 15, s = (p >> 5) & 1023;
        int j = g_ball[p];
        int c3 = (b * SS + s) * 3;
        float cx = g_new_xyz[c3], cy = g_new_xyz[c3 + 1], cz = g_new_xyz[c3 + 2];
        const float* X = xyz + b * 3 * NN;
        const float* P = pts + b * 3 * NN;
        float x0 = X[j] - cx, x1 = X[NN + j] - cy, x2 = X[2 * NN + j] - cz;
        float x3 = P[j], x4 = P[NN + j], x5 = P[2 * NN + j];
        #pragma unroll 8
        for (int o = 0; o < 64; o++) {
            const float* wr = w0 + o * 6;
            float a = b0[o];
            a = fmaf(wr[0], x0, a); a = fmaf(wr[1], x1, a); a = fmaf(wr[2], x2, a);
            a = fmaf(wr[3], x3, a); a = fmaf(wr[4], x4, a); a = fmaf(wr[5], x5, a);
            float z = fmaf(a, g_sc0[o], g_sh0[o]);
            Zsh[o][t] = fmaxf(z, 0.f);
        }
    }

    int po = t & 31, og = t >> 5;
    int o0 = og * 8;
    ull acc[4][4];
    #pragma unroll
    for (int op = 0; op < 4; op++) {
        ull bb = pack2(b1[o0 + 2 * op], b1[o0 + 2 * op + 1]);
        #pragma unroll
        for (int pp = 0; pp < 4; pp++) acc[op][pp] = bb;
    }

    for (int ch = 0; ch < 64; ch += 32) {
        __syncthreads();
        for (int L = t; L < 4096; L += 256) {
            int o = L >> 6, c = L & 63;
            if ((c & 32) == ch) Wsh[c & 31][o] = w1[L];
        }
        __syncthreads();
        #pragma unroll
        for (int cc = 0; cc < 32; cc++) {
            float4 z4 = *reinterpret_cast<const float4*>(&Zsh[ch + cc][po << 2]);
            ull zd[4] = { pack2(z4.x, z4.x), pack2(z4.y, z4.y),
                          pack2(z4.z, z4.z), pack2(z4.w, z4.w) };
            const ulonglong2* wp = reinterpret_cast<const ulonglong2*>(&Wsh[cc][o0]);
            ulonglong2 wA = wp[0], wB = wp[1];
            ull wv[4] = { wA.x, wA.y, wB.x, wB.y };
            #pragma unroll
            for (int op = 0; op < 4; op++)
                #pragma unroll
                for (int pp = 0; pp < 4; pp++)
                    acc[op][pp] = fma2(wv[op], zd[pp], acc[op][pp]);
        }
    }

    int pcol = pbase + (po << 2);
    float sum[8], sq[8];
    #pragma unroll
    for (int op = 0; op < 4; op++) {
        float lo[4], hi[4];
        #pragma unroll
        for (int pp = 0; pp < 4; pp++) unpack2(acc[op][pp], lo[pp], hi[pp]);
        float4 v0 = { lo[0], lo[1], lo[2], lo[3] };
        float4 v1 = { hi[0], hi[1], hi[2], hi[3] };
        *reinterpret_cast<float4*>(&g_y1[(o0 + 2 * op) * NPOS + pcol]) = v0;
        *reinterpret_cast<float4*>(&g_y1[(o0 + 2 * op + 1) * NPOS + pcol]) = v1;
        sum[2 * op]     = lo[0] + lo[1] + lo[2] + lo[3];
        sum[2 * op + 1] = hi[0] + hi[1] + hi[2] + hi[3];
        sq[2 * op]      = lo[0]*lo[0] + lo[1]*lo[1] + lo[2]*lo[2] + lo[3]*lo[3];
        sq[2 * op + 1]  = hi[0]*hi[0] + hi[1]*hi[1] + hi[2]*hi[2] + hi[3]*hi[3];
    }
    #pragma unroll
    for (int i = 0; i < 8; i++) { sum[i] = wredsum(sum[i]); sq[i] = wredsum(sq[i]); }
    if ((t & 31) == 0) {
        #pragma unroll
        for (int i = 0; i < 8; i++) {
            atomicAdd(&g_s1[o0 + i], sum[i]);
            atomicAdd(&g_s1[64 + o0 + i], sq[i]);
        }
    }
}

// ---------------- K6/K8: finalize BN stats ---------------------------------
__global__ void k_fin1(const float* __restrict__ g, const float* __restrict__ be) {
    int o = threadIdx.x;
    if (o >= 64) return;
    float inv = 1.f / (float)NPOS;
    float m = g_s1[o] * inv;
    float var = g_s1[64 + o] * inv - m * m;
    float sc = g[o] * rsqrtf(var + EPSV);
    g_sc1[o] = sc; g_sh1[o] = be[o] - m * sc;
}
__global__ void k_fin2(const float* __restrict__ g, const float* __restrict__ be) {
    int o = threadIdx.x;
    if (o >= 128) return;
    float inv = 1.f / (float)NPOS;
    float m = g_s2[o] * inv;
    float var = g_s2[128 + o] * inv - m * m;
    float sc = g[o] * rsqrtf(var + EPSV);
    g_sc2[o] = sc; g_sh2[o] = be[o] - m * sc;
}

// ---------------- K7: BN1 + relu + GEMM2 + in-block k-max/min --------------
__global__ void __launch_bounds__(256) k_layer2(const float* __restrict__ w2,
                                                const float* __restrict__ b2)
{
    __shared__ __align__(16) float Zsh[32][128];
    __shared__ __align__(16) float Wsh[32][132];
    int t = threadIdx.x;
    int pbase = blockIdx.x * 128;
    int po = t & 31, og = t >> 5;
    int o0 = og * 16;

    ull acc[8][4];
    #pragma unroll
    for (int op = 0; op < 8; op++) {
        ull bb = pack2(b2[o0 + 2 * op], b2[o0 + 2 * op + 1]);
        #pragma unroll
        for (int pp = 0; pp < 4; pp++) acc[op][pp] = bb;
    }

    for (int ch = 0; ch < 64; ch += 32) {
        __syncthreads();
        for (int i = t; i < 4096; i += 256) {
            int c = i >> 7, pc = i & 127;
            float y = g_y1[(ch + c) * NPOS + pbase + pc];
            Zsh[c][pc] = fmaxf(fmaf(y, g_sc1[ch + c], g_sh1[ch + c]), 0.f);
        }
        for (int L = t; L < 8192; L += 256) {
            int o = L >> 6, c = L & 63;
            if ((c & 32) == ch) Wsh[c & 31][o] = w2[L];
        }
        __syncthreads();
        #pragma unroll
        for (int cc = 0; cc < 32; cc++) {
            float4 z4 = *reinterpret_cast<const float4*>(&Zsh[cc][po << 2]);
            ull zd[4] = { pack2(z4.x, z4.x), pack2(z4.y, z4.y),
                          pack2(z4.z, z4.z), pack2(z4.w, z4.w) };
            const ulonglong2* wp = reinterpret_cast<const ulonglong2*>(&Wsh[cc][o0]);
            ulonglong2 wA = wp[0], wB = wp[1], wC = wp[2], wD = wp[3];
            ull wv[8] = { wA.x, wA.y, wB.x, wB.y, wC.x, wC.y, wD.x, wD.y };
            #pragma unroll
            for (int op = 0; op < 8; op++)
                #pragma unroll
                for (int pp = 0; pp < 4; pp++)
                    acc[op][pp] = fma2(wv[op], zd[pp], acc[op][pp]);
        }
    }

    // epilogue: BN stats sums + per-(b,o,s) raw max/min (32 k-samples live in
    // the 8-lane group: lanes g*8..g*8+7 each hold 4 consecutive positions)
    int p0 = pbase + ((po >> 3) << 5);           // first position of my s-group
    int bI = p0 >> 15, sI = (p0 >> 5) & 1023;
    int mbase = bI * (128 * SS) + sI;            // + o*SS for channel o
    float sum[16], sq[16];
    #pragma unroll
    for (int op = 0; op < 8; op++) {
        float lo[4], hi[4];
        #pragma unroll
        for (int pp = 0; pp < 4; pp++) unpack2(acc[op][pp], lo[pp], hi[pp]);
        sum[2 * op]     = lo[0] + lo[1] + lo[2] + lo[3];
        sum[2 * op + 1] = hi[0] + hi[1] + hi[2] + hi[3];
        sq[2 * op]      = lo[0]*lo[0] + lo[1]*lo[1] + lo[2]*lo[2] + lo[3]*lo[3];
        sq[2 * op + 1]  = hi[0]*hi[0] + hi[1]*hi[1] + hi[2]*hi[2] + hi[3]*hi[3];
        float mxl = fmaxf(fmaxf(lo[0], lo[1]), fmaxf(lo[2], lo[3]));
        float mnl = fminf(fminf(lo[0], lo[1]), fminf(lo[2], lo[3]));
        float mxh = fmaxf(fmaxf(hi[0], hi[1]), fmaxf(hi[2], hi[3]));
        float mnh = fminf(fminf(hi[0], hi[1]), fminf(hi[2], hi[3]));
        #pragma unroll
        for (int off = 1; off < 8; off <<= 1) {
            mxl = fmaxf(mxl, __shfl_xor_sync(0xffffffffu, mxl, off));
            mnl = fminf(mnl, __shfl_xor_sync(0xffffffffu, mnl, off));
            mxh = fmaxf(mxh, __shfl_xor_sync(0xffffffffu, mxh, off));
            mnh = fminf(mnh, __shfl_xor_sync(0xffffffffu, mnh, off));
        }
        if ((po & 7) == 0) {
            int iL = mbase + (o0 + 2 * op) * SS;
            int iH = mbase + (o0 + 2 * op + 1) * SS;
            g_m2mx[iL] = mxl; g_m2mn[iL] = mnl;
            g_m2mx[iH] = mxh; g_m2mn[iH] = mnh;
        }
    }
    #pragma unroll
    for (int i = 0; i < 16; i++) { sum[i] = wredsum(sum[i]); sq[i] = wredsum(sq[i]); }
    if ((t & 31) == 0) {
        #pragma unroll
        for (int i = 0; i < 16; i++) {
            atomicAdd(&g_s2[o0 + i], sum[i]);
            atomicAdd(&g_s2[128 + o0 + i], sq[i]);
        }
    }
}

// ---------------- K9: BN2 + relu on pre-reduced extremes -------------------
__global__ void k_max(float* __restrict__ out) {
    int m = blockIdx.x * blockDim.x + threadIdx.x;   // NFEAT threads
    int o = (m >> 10) & 127;
    float sc = g_sc2[o], sh = g_sh2[o];
    float v = (sc >= 0.f) ? g_m2mx[m] : g_m2mn[m];   // monotone BN: extreme maps
    out[OUT1 + m] = fmaxf(fmaf(v, sc, sh), 0.f);
}

// ---------------- launch ---------------------------------------------------
extern "C" void kernel_launch(void* const* d_in, const int* in_sizes, int n_in,
                              void* d_out, int out_size) {
    const float* xyz = (const float*)d_in[0];
    const float* pts = (const float*)d_in[1];
    const float* w0  = (const float*)d_in[2];
    const float* b0  = (const float*)d_in[3];
    const float* g0  = (const float*)d_in[4];
    const float* be0 = (const float*)d_in[5];
    const float* w1  = (const float*)d_in[6];
    const float* b1  = (const float*)d_in[7];
    const float* g1  = (const float*)d_in[8];
    const float* be1 = (const float*)d_in[9];
    const float* w2  = (const float*)d_in[10];
    const float* b2  = (const float*)d_in[11];
    const float* g2  = (const float*)d_in[12];
    const float* be2 = (const float*)d_in[13];
    float* out = (float*)d_out;
    (void)in_sizes; (void)n_in; (void)out_size;

    k_zero   <<<1, 256>>>();
    k_fps    <<<BB, 1024>>>(xyz, out);
    k_ball   <<<(BB * SS * 32) / 256, 256>>>(xyz);
    k_xstat  <<<NPOS / 256, 256>>>(xyz, pts);
    k_fin0   <<<1, 64>>>(w0, b0, g0, be0);
    k_layer1 <<<NPOS / 128, 256>>>(xyz, pts, w0, b0, w1, b1);
    k_fin1   <<<1, 64>>>(g1, be1);
    k_layer2 <<<NPOS / 128, 256>>>(w2, b2);
    k_fin2   <<<1, 128>>>(g2, be2);
    k_max    <<<NFEAT / 256, 256>>>(out);
}

// round 7
// speedup vs baseline: 1.4991x; 1.3627x over previous
#include <cuda_runtime.h>

#define BB 16
#define NN 4096
#define SS 1024
#define KK 32
#define NPOS (BB*SS*KK)      /* 524288 */
#define OUT1 (BB*3*SS)       /* 49152  */
#define NFEAT (BB*128*SS)    /* 2097152 */
#define R2C 0.04f
#define EPSV 1e-5f

typedef unsigned long long ull;

// ---------------- scratch (device globals; no allocation allowed) ----------
__device__ float g_new_xyz[BB*SS*3];
__device__ int   g_ball[NPOS];
__device__ int   g_prog[BB];       // FPS progress counters (centroids done)
__device__ __align__(16) float g_y1[64*NPOS];    // 134 MB
__device__ float g_m2mx[NFEAT];    // raw y2 max over k, 8 MB
__device__ float g_m2mn[NFEAT];    // raw y2 min over k, 8 MB
__device__ float g_xstat[27];
__device__ float g_s1[128];
__device__ float g_s2[256];
__device__ float g_sc0[64], g_sh0[64];
__device__ float g_sc1[64], g_sh1[64];
__device__ float g_sc2[128], g_sh2[128];

// ---------------- f32x2 helpers (Blackwell packed ops) ---------------------
__device__ __forceinline__ ull pack2(float lo, float hi) {
    ull r; asm("mov.b64 %0, {%1,%2};" : "=l"(r) : "f"(lo), "f"(hi)); return r;
}
__device__ __forceinline__ void unpack2(ull v, float& lo, float& hi) {
    asm("mov.b64 {%0,%1}, %2;" : "=f"(lo), "=f"(hi) : "l"(v));
}
__device__ __forceinline__ ull fma2(ull a, ull b, ull c) {
    ull d; asm("fma.rn.f32x2 %0, %1, %2, %3;" : "=l"(d) : "l"(a), "l"(b), "l"(c));
    return d;
}
__device__ __forceinline__ ull add2(ull a, ull b) {
    ull d; asm("add.rn.f32x2 %0, %1, %2;" : "=l"(d) : "l"(a), "l"(b)); return d;
}
__device__ __forceinline__ ull mul2(ull a, ull b) {
    ull d; asm("mul.rn.f32x2 %0, %1, %2;" : "=l"(d) : "l"(a), "l"(b)); return d;
}
__device__ __forceinline__ float wredsum(float v) {
    #pragma unroll
    for (int o = 16; o; o >>= 1) v += __shfl_down_sync(0xffffffffu, v, o);
    return v;
}

// ---------------- K0: zero stats + progress --------------------------------
__global__ void k_zero() {
    int t = threadIdx.x;
    if (t < 27)  g_xstat[t] = 0.f;
    if (t < 128) g_s1[t] = 0.f;
    if (t < 256) g_s2[t] = 0.f;
    if (t < BB)  g_prog[t] = 0;
}

// ---------------- K1: heterogeneous sampler --------------------------------
// bid < 16  : FPS for batch bid (redux argmax, 1 barrier/iter, progress pub)
// bid >= 16 : 32 ball-query warps + fused moment accumulation, pipelined on
//             the per-batch progress counter.
__global__ void __launch_bounds__(1024) k_sample(const float* __restrict__ xyz,
                                                 const float* __restrict__ pts,
                                                 float* __restrict__ out) {
    int bid = blockIdx.x, t = threadIdx.x;
    int lane = t & 31, wid = t >> 5;

    if (bid < BB) {
        // ------------------------- FPS role -------------------------------
        __shared__ unsigned swv[2][32];
        __shared__ unsigned swi[2][32];
        int b = bid;
        const float* X = xyz + b * 3 * NN;
        float px[4], py[4], pz[4], dd[4];
        #pragma unroll
        for (int i = 0; i < 4; i++) {
            int n = t + i * 1024;
            px[i] = X[n]; py[i] = X[NN + n]; pz[i] = X[2 * NN + n];
            dd[i] = 1e10f;
        }
        ull px2[2] = { pack2(px[0], px[1]), pack2(px[2], px[3]) };
        ull py2[2] = { pack2(py[0], py[1]), pack2(py[2], py[3]) };
        ull pz2[2] = { pack2(pz[0], pz[1]), pack2(pz[2], pz[3]) };

        float cx = X[0], cy = X[NN], cz = X[2 * NN];
        int par = 0;
        for (int it = 0; it < SS; it++) {
            if (t == 0) {
                int base = (b * SS + it) * 3;
                g_new_xyz[base + 0] = cx; g_new_xyz[base + 1] = cy; g_new_xyz[base + 2] = cz;
                out[b * 3 * SS + it]          = cx;
                out[b * 3 * SS + SS + it]     = cy;
                out[b * 3 * SS + 2 * SS + it] = cz;
                if ((it & 63) == 63) {          // publish centroids [0, it]
                    __threadfence();
                    atomicExch(&g_prog[b], it + 1);
                }
            }
            ull ncx = pack2(-cx, -cx), ncy = pack2(-cy, -cy), ncz = pack2(-cz, -cz);
            float n4[4];
            #pragma unroll
            for (int j = 0; j < 2; j++) {
                ull dx = add2(px2[j], ncx), dy = add2(py2[j], ncy), dz = add2(pz2[j], ncz);
                ull d2 = add2(add2(mul2(dx, dx), mul2(dy, dy)), mul2(dz, dz));
                float d0, d1; unpack2(d2, d0, d1);
                n4[2 * j]     = fminf(dd[2 * j], d0);     dd[2 * j]     = n4[2 * j];
                n4[2 * j + 1] = fminf(dd[2 * j + 1], d1); dd[2 * j + 1] = n4[2 * j + 1];
            }
            float bv = fmaxf(fmaxf(n4[0], n4[1]), fmaxf(n4[2], n4[3]));
            unsigned ci = 0x7fffffffu;
            #pragma unroll
            for (int jj = 3; jj >= 0; jj--)
                if (n4[jj] == bv) ci = (unsigned)(t + jj * 1024);  // ends at min idx
            unsigned vb = __float_as_uint(bv);                     // >=0: monotone
            unsigned wmax = __reduce_max_sync(0xffffffffu, vb);
            unsigned cc = (vb == wmax) ? ci : 0x7fffffffu;
            unsigned wmin = __reduce_min_sync(0xffffffffu, cc);
            if (lane == 0) { swv[par][wid] = wmax; swi[par][wid] = wmin; }
            __syncthreads();
            unsigned fvb = swv[par][lane];
            unsigned fib = swi[par][lane];
            unsigned gmax = __reduce_max_sync(0xffffffffu, fvb);
            unsigned c2 = (fvb == gmax) ? fib : 0x7fffffffu;
            unsigned gi = __reduce_min_sync(0xffffffffu, c2);
            cx = X[gi]; cy = X[NN + gi]; cz = X[2 * NN + gi];      // broadcast LDG
            par ^= 1;
        }
        if (t == 0) { __threadfence(); atomicExch(&g_prog[b], SS); }
    } else {
        // --------------------- ball + moments role ------------------------
        __shared__ int   sdst[1024];
        __shared__ float sacc[27];
        int w = (bid - BB) * 32 + wid;          // centroid id
        int b = w >> 10, s = w & 1023;
        if (t < 27) sacc[t] = 0.f;
        __syncthreads();

        if (lane == 0) {
            while ((unsigned)atomicAdd(&g_prog[b], 0) <= (unsigned)s) __nanosleep(256);
        }
        __syncwarp();
        __threadfence();                        // acquire centroid data

        int c3 = w * 3;
        float cx = g_new_xyz[c3], cy = g_new_xyz[c3 + 1], cz = g_new_xyz[c3 + 2];
        float s1 = __fadd_rn(__fadd_rn(__fmul_rn(cx, cx), __fmul_rn(cy, cy)), __fmul_rn(cz, cz));
        const float* X = xyz + b * 3 * NN;
        const float* P = pts + b * 3 * NN;
        int* dsts = sdst + wid * 32;
        int cnt = 0, first = 0;
        bool haveFirst = false;
        for (int base = 0; base < NN; base += 32) {
            int n = base + lane;
            float px = X[n], py = X[NN + n], pz = X[2 * NN + n];
            float dot = __fadd_rn(__fadd_rn(__fmul_rn(cx, px), __fmul_rn(cy, py)), __fmul_rn(cz, pz));
            float s2 = __fadd_rn(__fadd_rn(__fmul_rn(px, px), __fmul_rn(py, py)), __fmul_rn(pz, pz));
            float d = __fadd_rn(__fadd_rn(__fmul_rn(-2.f, dot), s1), s2);
            bool in = (d <= R2C);
            unsigned m = __ballot_sync(0xffffffffu, in);
            if (!haveFirst && m) { first = base + __ffs(m) - 1; haveFirst = true; }
            int pos = cnt + __popc(m & ((1u << lane) - 1));
            if (in && pos < KK) dsts[pos] = n;
            cnt += __popc(m);
            if (cnt >= KK) break;
        }
        int filled = min(cnt, KK);
        for (int q = filled + lane; q < KK; q += 32) dsts[q] = first;
        __syncwarp();

        int j = dsts[lane];
        g_ball[w * KK + lane] = j;              // coalesced

        // fused input-moment accumulation for this centroid's 32 samples
        float x[6];
        x[0] = X[j] - cx; x[1] = X[NN + j] - cy; x[2] = X[2 * NN + j] - cz;
        x[3] = P[j];      x[4] = P[NN + j];      x[5] = P[2 * NN + j];
        float v[27];
        #pragma unroll
        for (int c = 0; c < 6; c++) v[c] = x[c];
        int idx = 6;
        #pragma unroll
        for (int c0 = 0; c0 < 6; c0++)
            #pragma unroll
            for (int c1 = c0; c1 < 6; c1++) v[idx++] = x[c0] * x[c1];
        #pragma unroll
        for (int i = 0; i < 27; i++) {
            float tt = wredsum(v[i]);
            if (lane == 0) atomicAdd(&sacc[i], tt);
        }
        __syncthreads();
        if (t < 27) atomicAdd(&g_xstat[t], sacc[t]);
    }
}

// ---------------- K4: analytic BN0 stats -----------------------------------
__global__ void k_fin0(const float* __restrict__ w0, const float* __restrict__ b0,
                       const float* __restrict__ g0, const float* __restrict__ be0) {
    int o = threadIdx.x;
    if (o >= 64) return;
    float inv = 1.f / (float)NPOS;
    float mx[6], M[6][6];
    for (int c = 0; c < 6; c++) mx[c] = g_xstat[c] * inv;
    int idx = 6;
    for (int c0 = 0; c0 < 6; c0++)
        for (int c1 = c0; c1 < 6; c1++) {
            float m = g_xstat[idx++] * inv;
            M[c0][c1] = m; M[c1][c0] = m;
        }
    float W[6];
    for (int c = 0; c < 6; c++) W[c] = w0[o * 6 + c];
    float wm = 0.f;
    for (int c = 0; c < 6; c++) wm += W[c] * mx[c];
    float quad = 0.f;
    for (int c0 = 0; c0 < 6; c0++)
        for (int c1 = 0; c1 < 6; c1++) quad += W[c0] * W[c1] * M[c0][c1];
    float mean = wm + b0[o];
    float var = quad - wm * wm;
    float sc = g0[o] * rsqrtf(var + EPSV);
    g_sc0[o] = sc;
    g_sh0[o] = be0[o] - mean * sc;
}

// ---------------- K5: fused gather + conv0 + BN0 + GEMM1 -------------------
__global__ void __launch_bounds__(256) k_layer1(
    const float* __restrict__ xyz, const float* __restrict__ pts,
    const float* __restrict__ w0, const float* __restrict__ b0,
    const float* __restrict__ w1, const float* __restrict__ b1)
{
    __shared__ __align__(16) float Zsh[64][128];   // 32 KB
    __shared__ __align__(16) float Wsh[32][68];    // 8.5 KB
    int t = threadIdx.x;
    int pbase = blockIdx.x * 128;

    if (t < 128) {
        int p = pbase + t;
        int b = p >> 15, s = (p >> 5) & 1023;
        int j = g_ball[p];
        int c3 = (b * SS + s) * 3;
        float cx = g_new_xyz[c3], cy = g_new_xyz[c3 + 1], cz = g_new_xyz[c3 + 2];
        const float* X = xyz + b * 3 * NN;
        const float* P = pts + b * 3 * NN;
        float x0 = X[j] - cx, x1 = X[NN + j] - cy, x2 = X[2 * NN + j] - cz;
        float x3 = P[j], x4 = P[NN + j], x5 = P[2 * NN + j];
        #pragma unroll 8
        for (int o = 0; o < 64; o++) {
            const float* wr = w0 + o * 6;
            float a = b0[o];
            a = fmaf(wr[0], x0, a); a = fmaf(wr[1], x1, a); a = fmaf(wr[2], x2, a);
            a = fmaf(wr[3], x3, a); a = fmaf(wr[4], x4, a); a = fmaf(wr[5], x5, a);
            float z = fmaf(a, g_sc0[o], g_sh0[o]);
            Zsh[o][t] = fmaxf(z, 0.f);
        }
    }

    int po = t & 31, og = t >> 5;
    int o0 = og * 8;
    ull acc[4][4];
    #pragma unroll
    for (int op = 0; op < 4; op++) {
        ull bb = pack2(b1[o0 + 2 * op], b1[o0 + 2 * op + 1]);
        #pragma unroll
        for (int pp = 0; pp < 4; pp++) acc[op][pp] = bb;
    }

    for (int ch = 0; ch < 64; ch += 32) {
        __syncthreads();
        for (int L = t; L < 4096; L += 256) {
            int o = L >> 6, c = L & 63;
            if ((c & 32) == ch) Wsh[c & 31][o] = w1[L];
        }
        __syncthreads();
        #pragma unroll
        for (int cc = 0; cc < 32; cc++) {
            float4 z4 = *reinterpret_cast<const float4*>(&Zsh[ch + cc][po << 2]);
            ull zd[4] = { pack2(z4.x, z4.x), pack2(z4.y, z4.y),
                          pack2(z4.z, z4.z), pack2(z4.w, z4.w) };
            const ulonglong2* wp = reinterpret_cast<const ulonglong2*>(&Wsh[cc][o0]);
            ulonglong2 wA = wp[0], wB = wp[1];
            ull wv[4] = { wA.x, wA.y, wB.x, wB.y };
            #pragma unroll
            for (int op = 0; op < 4; op++)
                #pragma unroll
                for (int pp = 0; pp < 4; pp++)
                    acc[op][pp] = fma2(wv[op], zd[pp], acc[op][pp]);
        }
    }

    int pcol = pbase + (po << 2);
    float sum[8], sq[8];
    #pragma unroll
    for (int op = 0; op < 4; op++) {
        float lo[4], hi[4];
        #pragma unroll
        for (int pp = 0; pp < 4; pp++) unpack2(acc[op][pp], lo[pp], hi[pp]);
        float4 v0 = { lo[0], lo[1], lo[2], lo[3] };
        float4 v1 = { hi[0], hi[1], hi[2], hi[3] };
        *reinterpret_cast<float4*>(&g_y1[(o0 + 2 * op) * NPOS + pcol]) = v0;
        *reinterpret_cast<float4*>(&g_y1[(o0 + 2 * op + 1) * NPOS + pcol]) = v1;
        sum[2 * op]     = lo[0] + lo[1] + lo[2] + lo[3];
        sum[2 * op + 1] = hi[0] + hi[1] + hi[2] + hi[3];
        sq[2 * op]      = lo[0]*lo[0] + lo[1]*lo[1] + lo[2]*lo[2] + lo[3]*lo[3];
        sq[2 * op + 1]  = hi[0]*hi[0] + hi[1]*hi[1] + hi[2]*hi[2] + hi[3]*hi[3];
    }
    #pragma unroll
    for (int i = 0; i < 8; i++) { sum[i] = wredsum(sum[i]); sq[i] = wredsum(sq[i]); }
    if ((t & 31) == 0) {
        #pragma unroll
        for (int i = 0; i < 8; i++) {
            atomicAdd(&g_s1[o0 + i], sum[i]);
            atomicAdd(&g_s1[64 + o0 + i], sq[i]);
        }
    }
}

// ---------------- K6/K8: finalize BN stats ---------------------------------
__global__ void k_fin1(const float* __restrict__ g, const float* __restrict__ be) {
    int o = threadIdx.x;
    if (o >= 64) return;
    float inv = 1.f / (float)NPOS;
    float m = g_s1[o] * inv;
    float var = g_s1[64 + o] * inv - m * m;
    float sc = g[o] * rsqrtf(var + EPSV);
    g_sc1[o] = sc; g_sh1[o] = be[o] - m * sc;
}
__global__ void k_fin2(const float* __restrict__ g, const float* __restrict__ be) {
    int o = threadIdx.x;
    if (o >= 128) return;
    float inv = 1.f / (float)NPOS;
    float m = g_s2[o] * inv;
    float var = g_s2[128 + o] * inv - m * m;
    float sc = g[o] * rsqrtf(var + EPSV);
    g_sc2[o] = sc; g_sh2[o] = be[o] - m * sc;
}

// ---------------- K7: BN1 + relu + GEMM2 + in-block k-max/min --------------
__global__ void __launch_bounds__(256) k_layer2(const float* __restrict__ w2,
                                                const float* __restrict__ b2)
{
    __shared__ __align__(16) float Zsh[32][128];
    __shared__ __align__(16) float Wsh[32][132];
    int t = threadIdx.x;
    int pbase = blockIdx.x * 128;
    int po = t & 31, og = t >> 5;
    int o0 = og * 16;

    ull acc[8][4];
    #pragma unroll
    for (int op = 0; op < 8; op++) {
        ull bb = pack2(b2[o0 + 2 * op], b2[o0 + 2 * op + 1]);
        #pragma unroll
        for (int pp = 0; pp < 4; pp++) acc[op][pp] = bb;
    }

    for (int ch = 0; ch < 64; ch += 32) {
        __syncthreads();
        for (int i = t; i < 4096; i += 256) {
            int c = i >> 7, pc = i & 127;
            float y = g_y1[(ch + c) * NPOS + pbase + pc];
            Zsh[c][pc] = fmaxf(fmaf(y, g_sc1[ch + c], g_sh1[ch + c]), 0.f);
        }
        for (int L = t; L < 8192; L += 256) {
            int o = L >> 6, c = L & 63;
            if ((c & 32) == ch) Wsh[c & 31][o] = w2[L];
        }
        __syncthreads();
        #pragma unroll
        for (int cc = 0; cc < 32; cc++) {
            float4 z4 = *reinterpret_cast<const float4*>(&Zsh[cc][po << 2]);
            ull zd[4] = { pack2(z4.x, z4.x), pack2(z4.y, z4.y),
                          pack2(z4.z, z4.z), pack2(z4.w, z4.w) };
            const ulonglong2* wp = reinterpret_cast<const ulonglong2*>(&Wsh[cc][o0]);
            ulonglong2 wA = wp[0], wB = wp[1], wC = wp[2], wD = wp[3];
            ull wv[8] = { wA.x, wA.y, wB.x, wB.y, wC.x, wC.y, wD.x, wD.y };
            #pragma unroll
            for (int op = 0; op < 8; op++)
                #pragma unroll
                for (int pp = 0; pp < 4; pp++)
                    acc[op][pp] = fma2(wv[op], zd[pp], acc[op][pp]);
        }
    }

    int p0 = pbase + ((po >> 3) << 5);
    int bI = p0 >> 15, sI = (p0 >> 5) & 1023;
    int mbase = bI * (128 * SS) + sI;
    float sum[16], sq[16];
    #pragma unroll
    for (int op = 0; op < 8; op++) {
        float lo[4], hi[4];
        #pragma unroll
        for (int pp = 0; pp < 4; pp++) unpack2(acc[op][pp], lo[pp], hi[pp]);
        sum[2 * op]     = lo[0] + lo[1] + lo[2] + lo[3];
        sum[2 * op + 1] = hi[0] + hi[1] + hi[2] + hi[3];
        sq[2 * op]      = lo[0]*lo[0] + lo[1]*lo[1] + lo[2]*lo[2] + lo[3]*lo[3];
        sq[2 * op + 1]  = hi[0]*hi[0] + hi[1]*hi[1] + hi[2]*hi[2] + hi[3]*hi[3];
        float mxl = fmaxf(fmaxf(lo[0], lo[1]), fmaxf(lo[2], lo[3]));
        float mnl = fminf(fminf(lo[0], lo[1]), fminf(lo[2], lo[3]));
        float mxh = fmaxf(fmaxf(hi[0], hi[1]), fmaxf(hi[2], hi[3]));
        float mnh = fminf(fminf(hi[0], hi[1]), fminf(hi[2], hi[3]));
        #pragma unroll
        for (int off = 1; off < 8; off <<= 1) {
            mxl = fmaxf(mxl, __shfl_xor_sync(0xffffffffu, mxl, off));
            mnl = fminf(mnl, __shfl_xor_sync(0xffffffffu, mnl, off));
            mxh = fmaxf(mxh, __shfl_xor_sync(0xffffffffu, mxh, off));
            mnh = fminf(mnh, __shfl_xor_sync(0xffffffffu, mnh, off));
        }
        if ((po & 7) == 0) {
            int iL = mbase + (o0 + 2 * op) * SS;
            int iH = mbase + (o0 + 2 * op + 1) * SS;
            g_m2mx[iL] = mxl; g_m2mn[iL] = mnl;
            g_m2mx[iH] = mxh; g_m2mn[iH] = mnh;
        }
    }
    #pragma unroll
    for (int i = 0; i < 16; i++) { sum[i] = wredsum(sum[i]); sq[i] = wredsum(sq[i]); }
    if ((t & 31) == 0) {
        #pragma unroll
        for (int i = 0; i < 16; i++) {
            atomicAdd(&g_s2[o0 + i], sum[i]);
            atomicAdd(&g_s2[128 + o0 + i], sq[i]);
        }
    }
}

// ---------------- K9: BN2 + relu on pre-reduced extremes -------------------
__global__ void k_max(float* __restrict__ out) {
    int m = blockIdx.x * blockDim.x + threadIdx.x;
    int o = (m >> 10) & 127;
    float sc = g_sc2[o], sh = g_sh2[o];
    float v = (sc >= 0.f) ? g_m2mx[m] : g_m2mn[m];
    out[OUT1 + m] = fmaxf(fmaf(v, sc, sh), 0.f);
}

// ---------------- launch ---------------------------------------------------
extern "C" void kernel_launch(void* const* d_in, const int* in_sizes, int n_in,
                              void* d_out, int out_size) {
    const float* xyz = (const float*)d_in[0];
    const float* pts = (const float*)d_in[1];
    const float* w0  = (const float*)d_in[2];
    const float* b0  = (const float*)d_in[3];
    const float* g0  = (const float*)d_in[4];
    const float* be0 = (const float*)d_in[5];
    const float* w1  = (const float*)d_in[6];
    const float* b1  = (const float*)d_in[7];
    const float* g1  = (const float*)d_in[8];
    const float* be1 = (const float*)d_in[9];
    const float* w2  = (const float*)d_in[10];
    const float* b2  = (const float*)d_in[11];
    const float* g2  = (const float*)d_in[12];
    const float* be2 = (const float*)d_in[13];
    float* out = (float*)d_out;
    (void)in_sizes; (void)n_in; (void)out_size;

    k_zero   <<<1, 256>>>();
    k_sample <<<BB + (BB * SS) / 32, 1024>>>(xyz, pts, out);
    k_fin0   <<<1, 64>>>(w0, b0, g0, be0);
    k_layer1 <<<NPOS / 128, 256>>>(xyz, pts, w0, b0, w1, b1);
    k_fin1   <<<1, 64>>>(g1, be1);
    k_layer2 <<<NPOS / 128, 256>>>(w2, b2);
    k_fin2   <<<1, 128>>>(g2, be2);
    k_max    <<<NFEAT / 256, 256>>>(out);
}